// round 7
// baseline (speedup 1.0000x reference)
#include <cuda_runtime.h>
#include <cuda_bf16.h>
#include <math.h>
#include <stdint.h>

// ---------------- problem constants ----------------
#define Bq 8
#define Sq 1024
#define Dq 1024
#define DAq 256
#define Hq 16
#define HDq 64
#define Rq 32
#define Mtok (Bq*Sq)   // 8192
#define NCAT (DAq + 3*Dq)   // 3328 fused output cols

// ---------------- scratch (device globals; no allocation) ----------------
__device__ float g_xr  [Mtok*Dq];
__device__ float g_WuT [Dq*Dq];
__device__ float g_WoT [Dq*Dq];
__device__ float g_WkselT[DAq*Dq];
__device__ float g_Wcat[NCAT*Dq];           // [qsel(256) | q | k | v] rows, K=1024
__device__ float g_pooled[Bq*Rq*Dq];
__device__ float g_root  [Bq*Rq*Dq];
__device__ float g_ksel  [Bq*Rq*DAq];
__device__ float g_qsel  [Mtok*DAq];
__device__ unsigned char g_mask[Mtok*Rq];
__device__ float g_q [Mtok*Dq];             // [B,H,S,64]
__device__ float g_k [Mtok*Dq];
__device__ float g_v [Mtok*Dq];
__device__ float g_ctx[Mtok*Dq];

// ---------------- helpers ----------------
__device__ __forceinline__ float rna_tf32(float x) {
    uint32_t r; asm("cvt.rna.tf32.f32 %0, %1;" : "=r"(r) : "f"(x));
    return __uint_as_float(r);
}
__device__ __forceinline__ float warp_max(float v) {
    #pragma unroll
    for (int o = 16; o; o >>= 1) v = fmaxf(v, __shfl_xor_sync(0xffffffffu, v, o));
    return v;
}
__device__ __forceinline__ float warp_sum(float v) {
    #pragma unroll
    for (int o = 16; o; o >>= 1) v += __shfl_xor_sync(0xffffffffu, v, o);
    return v;
}
__device__ __forceinline__ uint32_t smem_u32(const void* p) {
    uint32_t a;
    asm("{ .reg .u64 t; cvta.to.shared.u64 t, %1; cvt.u32.u64 %0, t; }" : "=r"(a) : "l"(p));
    return a;
}

#define CP16(dst, src) \
    asm volatile("cp.async.cg.shared.global [%0], [%1], 16;" :: "r"(dst), "l"(src))
#define CPCOMMIT() asm volatile("cp.async.commit_group;")
#define CPWAIT(n)  asm volatile("cp.async.wait_group %0;" :: "n"(n))

#define LDSM4(r0, r1, r2, r3, addr) \
    asm volatile("ldmatrix.sync.aligned.m8n8.x4.shared.b16 {%0,%1,%2,%3}, [%4];" \
        : "=r"(r0), "=r"(r1), "=r"(r2), "=r"(r3) : "r"(addr))

__device__ __forceinline__ void mma_tf32(float c[4], const uint32_t a[4], const uint32_t b[2]) {
    asm volatile(
        "mma.sync.aligned.m16n8k8.row.col.f32.tf32.tf32.f32 "
        "{%0,%1,%2,%3}, {%4,%5,%6,%7}, {%8,%9}, {%0,%1,%2,%3};"
        : "+f"(c[0]), "+f"(c[1]), "+f"(c[2]), "+f"(c[3])
        : "r"(a[0]), "r"(a[1]), "r"(a[2]), "r"(a[3]), "r"(b[0]), "r"(b[1]));
}

// ---------------- prep kernels ----------------
__global__ void round_copy_kernel(const float4* __restrict__ in, float4* __restrict__ out, int n4) {
    int i = blockIdx.x * blockDim.x + threadIdx.x;
    if (i < n4) {
        float4 v = in[i];
        v.x = rna_tf32(v.x); v.y = rna_tf32(v.y); v.z = rna_tf32(v.z); v.w = rna_tf32(v.w);
        out[i] = v;
    }
}

// W[K,N] -> Wt[N,K] with tf32 rounding. grid(N/32, K/32), block(32,8)
__global__ void transpose_round_kernel(const float* __restrict__ W, float* __restrict__ Wt,
                                       int Kdim, int Ndim) {
    __shared__ float t[32][33];
    int n0 = blockIdx.x * 32, k0 = blockIdx.y * 32;
    int tx = threadIdx.x, ty = threadIdx.y;
    #pragma unroll
    for (int i = 0; i < 32; i += 8)
        t[ty + i][tx] = W[(size_t)(k0 + ty + i) * Ndim + n0 + tx];
    __syncthreads();
    #pragma unroll
    for (int i = 0; i < 32; i += 8)
        Wt[(size_t)(n0 + ty + i) * Kdim + k0 + tx] = rna_tf32(t[tx][ty + i]);
}

__global__ void pool_kernel(const float* __restrict__ x, float* __restrict__ pooled) {
    int br = blockIdx.x;
    const float* base = x + (size_t)br * 32 * Dq;
    int d4 = threadIdx.x;
    float4 acc = make_float4(0.f, 0.f, 0.f, 0.f);
    #pragma unroll 4
    for (int i = 0; i < 32; i++) {
        float4 v = *(const float4*)(base + (size_t)i * Dq + d4 * 4);
        acc.x += v.x; acc.y += v.y; acc.z += v.z; acc.w += v.w;
    }
    const float s = 1.0f / 32.0f;
    acc.x = rna_tf32(acc.x * s); acc.y = rna_tf32(acc.y * s);
    acc.z = rna_tf32(acc.z * s); acc.w = rna_tf32(acc.w * s);
    *(float4*)(pooled + (size_t)br * Dq + d4 * 4) = acc;
}

// ---------------- tf32 mma.sync GEMM: 64x64 warp tiles, 3-stage pipeline ----------------
// C[M,N] = A[M,K] @ Bt[N,K]^T
// modes: 0 plain, 2 +resid, 3 store rounded, 4 fused routing (qsel/q/k/v)
#define GBM 128
#define GBN 128
#define GBK 32
#define LDT 36
#define STAGE_FLOATS (256 * LDT)            // A(128 rows) + B(128 rows), 9216 floats
#define SM_GEMM_BYTES (3 * STAGE_FLOATS * 4)  // 110592 B

__global__ __launch_bounds__(128, 2)
void mma_gemm(const float* __restrict__ A, const float* __restrict__ Bt,
              float* __restrict__ C, int M, int N, int Kd,
              int mode, const float* __restrict__ resid,
              float* __restrict__ pq, float* __restrict__ pk, float* __restrict__ pv)
{
    extern __shared__ float smf[];
    int tid = threadIdx.x;
    int wid = tid >> 5, lane = tid & 31;
    int warp_row = wid & 1;        // 2 warps along M (64 rows each)
    int warp_col = wid >> 1;       // 2 warps along N (64 cols each)
    int gr = lane >> 2, gc = lane & 3;
    int bm = blockIdx.y * GBM;
    int bn = blockIdx.x * GBN;

    // ldmatrix per-thread tile-row addressing
    int sel = lane >> 3, l8 = lane & 7;
    int a_row_off = (sel & 1) * 8 + l8;
    int a_col_off = (sel >> 1) * 4;
    int b_row_off = (sel >> 1) * 8 + l8;
    int b_col_off = (sel & 1) * 4;

    float c[4][8][4];
    #pragma unroll
    for (int f = 0; f < 4; f++)
        #pragma unroll
        for (int g = 0; g < 8; g++)
            #pragma unroll
            for (int i = 0; i < 4; i++) c[f][g][i] = 0.f;

    uint32_t sbase = smem_u32(smf);
    const int NK = Kd / GBK;

    // loader: one stage = 128 A rows + 128 B rows, 2048 cp16 / 128 thr = 16 each
    auto load_stage = [&](int st, int k0) {
        uint32_t Abase = sbase + (uint32_t)(st * STAGE_FLOATS) * 4;
        uint32_t Bbase = Abase + (uint32_t)(128 * LDT) * 4;
        #pragma unroll
        for (int j = 0; j < 8; j++) {
            int idx = tid + j * 128;
            int row = idx >> 3, kc = idx & 7;
            CP16(Abase + (uint32_t)(row * LDT + kc * 4) * 4,
                 A + (size_t)(bm + row) * Kd + k0 + kc * 4);
        }
        #pragma unroll
        for (int j = 0; j < 8; j++) {
            int idx = tid + j * 128;
            int row = idx >> 3, kc = idx & 7;
            CP16(Bbase + (uint32_t)(row * LDT + kc * 4) * 4,
                 Bt + (size_t)(bn + row) * Kd + k0 + kc * 4);
        }
    };

    load_stage(0, 0);
    CPCOMMIT();
    load_stage(1, GBK);
    CPCOMMIT();

    for (int ks = 0; ks < NK; ks++) {
        int st = ks - (ks / 3) * 3;          // ks % 3
        if (ks + 1 < NK) CPWAIT(1); else CPWAIT(0);
        __syncthreads();
        if (ks + 2 < NK) {
            int st2 = (ks + 2) - ((ks + 2) / 3) * 3;
            load_stage(st2, (ks + 2) * GBK);
            CPCOMMIT();
        }

        uint32_t As = sbase + (uint32_t)(st * STAGE_FLOATS) * 4;
        uint32_t Bs = As + (uint32_t)(128 * LDT) * 4;
        uint32_t aAddr = As + (uint32_t)((warp_row * 64 + a_row_off) * LDT + a_col_off) * 4;
        uint32_t bAddr = Bs + (uint32_t)((warp_col * 64 + b_row_off) * LDT + b_col_off) * 4;

        #pragma unroll
        for (int kk = 0; kk < 4; kk++) {
            uint32_t a[4][4], b[8][2];
            #pragma unroll
            for (int f = 0; f < 4; f++)
                LDSM4(a[f][0], a[f][1], a[f][2], a[f][3],
                      aAddr + (uint32_t)(f * 16 * LDT + kk * 8) * 4);
            #pragma unroll
            for (int gp = 0; gp < 4; gp++)
                LDSM4(b[2*gp][0], b[2*gp][1], b[2*gp+1][0], b[2*gp+1][1],
                      bAddr + (uint32_t)(gp * 16 * LDT + kk * 8) * 4);
            #pragma unroll
            for (int f = 0; f < 4; f++)
                #pragma unroll
                for (int g = 0; g < 8; g++)
                    mma_tf32(c[f][g], a[f], b[g]);
        }
    }
    __syncthreads();   // all compute done before reusing smem for epilogue

    // ---- epilogue: stage 128x128 in smem, coalesced routing stores ----
    float* stg = smf;   // 128*132*4 = 67584 <= 110592
    #pragma unroll
    for (int f = 0; f < 4; f++) {
        #pragma unroll
        for (int g = 0; g < 8; g++) {
            int r0 = warp_row * 64 + f * 16 + gr;
            int c0 = warp_col * 64 + g * 8 + 2 * gc;
            stg[r0 * 132 + c0]           = c[f][g][0];
            stg[r0 * 132 + c0 + 1]       = c[f][g][1];
            stg[(r0 + 8) * 132 + c0]     = c[f][g][2];
            stg[(r0 + 8) * 132 + c0 + 1] = c[f][g][3];
        }
    }
    __syncthreads();

    int ccol = (tid & 31) * 4;
    #pragma unroll 8
    for (int rr = 0; rr < 32; rr++) {
        int r = (tid >> 5) + rr * 4;
        float4 v;
        v.x = stg[r * 132 + ccol + 0];
        v.y = stg[r * 132 + ccol + 1];
        v.z = stg[r * 132 + ccol + 2];
        v.w = stg[r * 132 + ccol + 3];
        int m = bm + r;
        int n = bn + ccol;
        if (mode == 0) {
            *(float4*)(C + (size_t)m * N + n) = v;
        } else if (mode == 2) {
            float4 rv = *(const float4*)(resid + (size_t)m * N + n);
            v.x += rv.x; v.y += rv.y; v.z += rv.z; v.w += rv.w;
            *(float4*)(C + (size_t)m * N + n) = v;
        } else if (mode == 3) {
            v.x = rna_tf32(v.x); v.y = rna_tf32(v.y);
            v.z = rna_tf32(v.z); v.w = rna_tf32(v.w);
            *(float4*)(C + (size_t)m * N + n) = v;
        } else {
            if (n < DAq) {
                *(float4*)(C + (size_t)m * DAq + n) = v;
            } else {
                int n2 = n - DAq;
                int proj = n2 >> 10, nn = n2 & 1023;
                int h = nn >> 6, hd = nn & 63;
                int b = m >> 10, s = m & 1023;
                float* P = (proj == 0) ? pq : (proj == 1) ? pk : pv;
                *(float4*)(P + (((size_t)(b * Hq + h)) * Sq + s) * HDq + hd) = v;
            }
        }
    }
}

// ---------------- block selection ----------------
__global__ __launch_bounds__(256) void select_kernel(
    const float* __restrict__ qsel, const float* __restrict__ ksel,
    unsigned char* __restrict__ mask)
{
    __shared__ float ks[Rq][DAq + 1];
    __shared__ float qrow[8][DAq];
    int b = blockIdx.x;
    int s0 = blockIdx.y * 8;
    int warp = threadIdx.x >> 5, lane = threadIdx.x & 31;
    int s = s0 + warp;

    const float* kp = ksel + (size_t)b * Rq * DAq;
    for (int i = threadIdx.x; i < Rq * DAq; i += 256)
        ks[i >> 8][i & 255] = kp[i];
    const float* qp = qsel + ((size_t)b * Sq + s) * DAq;
    for (int d = lane; d < DAq; d += 32) qrow[warp][d] = qp[d];
    __syncthreads();

    float logit = 0.f;
    #pragma unroll 8
    for (int d = 0; d < DAq; d++)
        logit += qrow[warp][d] * ks[lane][d];
    logit *= 0.0625f;

    float mx = warp_max(logit);
    float e = expf(logit - mx);
    float sum = warp_sum(e);
    float prob = e / sum;
    bool own = (s >> 5) == lane;
    mask[((size_t)b * Sq + s) * Rq + lane] = (prob >= 0.5f || own) ? 1 : 0;
}

// ---------------- block-sparse attention (32 queries per CTA) ----------------
__global__ __launch_bounds__(256) void attn_kernel(
    const float* __restrict__ Q, const float* __restrict__ K,
    const float* __restrict__ V, const unsigned char* __restrict__ mask,
    float* __restrict__ ctx)
{
    __shared__ float qs[32][68];
    __shared__ float kt[32][68];
    __shared__ float vt[32][68];
    __shared__ uint32_t qbits[32];
    __shared__ uint32_t needm_s;

    int bh = blockIdx.x;
    int b = bh >> 4, h = bh & 15;
    int qb = blockIdx.y;
    int s0 = qb * 32;
    int tid = threadIdx.x, warp = tid >> 5, lane = tid & 31;

    const float* Qb = Q + ((size_t)bh * Sq + s0) * HDq;
    #pragma unroll
    for (int i = 0; i < 2; i++) {
        int idx = tid + i * 256;
        int row = idx >> 4, col = (idx & 15) << 2;
        float4 f = *(const float4*)(Qb + row * HDq + col);
        qs[row][col] = f.x; qs[row][col+1] = f.y; qs[row][col+2] = f.z; qs[row][col+3] = f.w;
    }

    if (warp == 0) {
        const unsigned char* mrow = mask + ((size_t)b * Sq + s0 + lane) * Rq;
        uint32_t bits = 0;
        #pragma unroll
        for (int r = 0; r < Rq; r++) bits |= (mrow[r] ? 1u : 0u) << r;
        qbits[lane] = bits;
        #pragma unroll
        for (int o = 16; o; o >>= 1) bits |= __shfl_xor_sync(0xffffffffu, bits, o);
        if (lane == 0) needm_s = bits;
    }
    __syncthreads();
    uint32_t need = needm_s;
    uint32_t myb[4];
    #pragma unroll
    for (int j = 0; j < 4; j++) myb[j] = qbits[warp * 4 + j];

    float mr[4], l[4], c0[4], c1[4];
    #pragma unroll
    for (int j = 0; j < 4; j++) { mr[j] = -INFINITY; l[j] = 0.f; c0[j] = 0.f; c1[j] = 0.f; }

    const float* kbh = K + (size_t)bh * Sq * HDq;
    const float* vbh = V + (size_t)bh * Sq * HDq;

    for (int r = 0; r < 32; r++) {
        if (!((need >> r) & 1u)) continue;
        __syncthreads();
        const float* kb = kbh + (size_t)r * 32 * HDq;
        const float* vb = vbh + (size_t)r * 32 * HDq;
        #pragma unroll
        for (int i = 0; i < 2; i++) {
            int idx = tid + i * 256;
            int row = idx >> 4, col = (idx & 15) << 2;
            float4 f = *(const float4*)(kb + row * HDq + col);
            kt[row][col] = f.x; kt[row][col+1] = f.y; kt[row][col+2] = f.z; kt[row][col+3] = f.w;
            float4 g = *(const float4*)(vb + row * HDq + col);
            vt[row][col] = g.x; vt[row][col+1] = g.y; vt[row][col+2] = g.z; vt[row][col+3] = g.w;
        }
        __syncthreads();

        #pragma unroll
        for (int j = 0; j < 4; j++) {
            if (!((myb[j] >> r) & 1u)) continue;
            int qi = warp * 4 + j;
            float sc = 0.f;
            #pragma unroll
            for (int d = 0; d < HDq; d += 4) {
                float4 kv = *(const float4*)&kt[lane][d];
                float4 qv = *(const float4*)&qs[qi][d];
                sc += kv.x * qv.x + kv.y * qv.y + kv.z * qv.z + kv.w * qv.w;
            }
            sc *= 0.125f;
            float bmax = warp_max(sc);
            float mnew = fmaxf(mr[j], bmax);
            float p = __expf(sc - mnew);
            float scale = __expf(mr[j] - mnew);
            l[j] = l[j] * scale + warp_sum(p);
            c0[j] *= scale; c1[j] *= scale;
            #pragma unroll 8
            for (int t = 0; t < 32; t++) {
                float pj = __shfl_sync(0xffffffffu, p, t);
                c0[j] += pj * vt[t][lane];
                c1[j] += pj * vt[t][lane + 32];
            }
            mr[j] = mnew;
        }
    }

    #pragma unroll
    for (int j = 0; j < 4; j++) {
        int s = s0 + warp * 4 + j;
        float inv = 1.0f / l[j];
        float* cp = ctx + ((size_t)(b * Sq + s)) * Dq + h * HDq;
        cp[lane] = rna_tf32(c0[j] * inv);
        cp[lane + 32] = rna_tf32(c1[j] * inv);
    }
}

// ---------------- host launch ----------------
extern "C" void kernel_launch(void* const* d_in, const int* in_sizes, int n_in,
                              void* d_out, int out_size) {
    const float* x      = (const float*)d_in[0];
    const float* Wu     = (const float*)d_in[1];
    const float* Wk_sel = (const float*)d_in[2];
    const float* Wq_sel = (const float*)d_in[3];
    const float* Wq     = (const float*)d_in[4];
    const float* Wk     = (const float*)d_in[5];
    const float* Wv     = (const float*)d_in[6];
    const float* Wo     = (const float*)d_in[7];
    float* out = (float*)d_out;

    float *xr, *WuT, *WoT, *WkselT, *Wcat;
    float *pooled, *root, *ksel, *qsel, *q, *k, *v, *ctx;
    unsigned char* mask;
    cudaGetSymbolAddress((void**)&xr,     g_xr);
    cudaGetSymbolAddress((void**)&WuT,    g_WuT);
    cudaGetSymbolAddress((void**)&WoT,    g_WoT);
    cudaGetSymbolAddress((void**)&WkselT, g_WkselT);
    cudaGetSymbolAddress((void**)&Wcat,   g_Wcat);
    cudaGetSymbolAddress((void**)&pooled, g_pooled);
    cudaGetSymbolAddress((void**)&root,   g_root);
    cudaGetSymbolAddress((void**)&ksel,   g_ksel);
    cudaGetSymbolAddress((void**)&qsel,   g_qsel);
    cudaGetSymbolAddress((void**)&mask,   g_mask);
    cudaGetSymbolAddress((void**)&q,      g_q);
    cudaGetSymbolAddress((void**)&k,      g_k);
    cudaGetSymbolAddress((void**)&v,      g_v);
    cudaGetSymbolAddress((void**)&ctx,    g_ctx);

    cudaFuncSetAttribute(mma_gemm, cudaFuncAttributeMaxDynamicSharedMemorySize, SM_GEMM_BYTES);

    // (1) round x
    round_copy_kernel<<<(Mtok * Dq / 4 + 255) / 256, 256>>>((const float4*)x, (float4*)xr, Mtok * Dq / 4);
    // (2-5) Wcat transposes
    transpose_round_kernel<<<dim3(DAq / 32, Dq / 32), dim3(32, 8)>>>(Wq_sel, Wcat, Dq, DAq);
    transpose_round_kernel<<<dim3(Dq / 32, Dq / 32), dim3(32, 8)>>>(Wq, Wcat + (size_t)DAq * Dq, Dq, Dq);
    transpose_round_kernel<<<dim3(Dq / 32, Dq / 32), dim3(32, 8)>>>(Wk, Wcat + (size_t)(DAq + Dq) * Dq, Dq, Dq);
    transpose_round_kernel<<<dim3(Dq / 32, Dq / 32), dim3(32, 8)>>>(Wv, Wcat + (size_t)(DAq + 2 * Dq) * Dq, Dq, Dq);
    // (6) fused: [qsel | q | k | v] = xr @ Wcat^T
    mma_gemm<<<dim3(NCAT / GBN, Mtok / GBM), 128, SM_GEMM_BYTES>>>(
        xr, Wcat, qsel, Mtok, NCAT, Dq, 4, nullptr, q, k, v);
    // (7-9) remaining transposes
    transpose_round_kernel<<<dim3(Dq / 32, Dq / 32), dim3(32, 8)>>>(Wu, WuT, Dq, Dq);
    transpose_round_kernel<<<dim3(Dq / 32, Dq / 32), dim3(32, 8)>>>(Wo, WoT, Dq, Dq);
    transpose_round_kernel<<<dim3(DAq / 32, Dq / 32), dim3(32, 8)>>>(Wk_sel, WkselT, Dq, DAq);
    // (10) pooling
    pool_kernel<<<Bq * Rq, 256>>>(x, pooled);
    // (11) root = pooled @ Wu
    mma_gemm<<<dim3(Dq / GBN, (Bq * Rq) / GBM), 128, SM_GEMM_BYTES>>>(
        pooled, WuT, root, Bq * Rq, Dq, Dq, 3, nullptr, nullptr, nullptr, nullptr);
    // (12) ksel = root @ Wk_sel
    mma_gemm<<<dim3(DAq / GBN, (Bq * Rq) / GBM), 128, SM_GEMM_BYTES>>>(
        root, WkselT, ksel, Bq * Rq, DAq, Dq, 0, nullptr, nullptr, nullptr, nullptr);
    // (13) selection mask
    select_kernel<<<dim3(Bq, Sq / 8), 256>>>(qsel, ksel, mask);
    // (14) attention
    attn_kernel<<<dim3(Bq * Hq, Sq / 32), 256>>>(q, k, v, mask, ctx);
    // (15) out = ctx @ Wo + x
    mma_gemm<<<dim3(Dq / GBN, Mtok / GBM), 128, SM_GEMM_BYTES>>>(
        ctx, WoT, out, Mtok, Dq, Dq, 2, x, nullptr, nullptr, nullptr);
}

// round 8
// speedup vs baseline: 1.1291x; 1.1291x over previous
#include <cuda_runtime.h>
#include <cuda_bf16.h>
#include <math.h>
#include <stdint.h>

// ---------------- problem constants ----------------
#define Bq 8
#define Sq 1024
#define Dq 1024
#define DAq 256
#define Hq 16
#define HDq 64
#define Rq 32
#define Mtok (Bq*Sq)   // 8192
#define NCAT (DAq + 3*Dq)   // 3328

// ---------------- scratch (device globals; no allocation) ----------------
__device__ float g_xr  [Mtok*Dq];
__device__ float g_WuT [Dq*Dq];
__device__ float g_WoT [Dq*Dq];
__device__ float g_WkselT[DAq*Dq];
__device__ float g_Wcat[NCAT*Dq];           // [qsel(256) | q | k | v] rows, K=1024
__device__ float g_pooled[Bq*Rq*Dq];
__device__ float g_root  [Bq*Rq*Dq];
__device__ float g_ksel  [Bq*Rq*DAq];
__device__ float g_part[4*256*1024];        // split-K partials (4 MB)
__device__ float g_qsel  [Mtok*DAq];
__device__ unsigned char g_mask[Mtok*Rq];
__device__ float g_q [Mtok*Dq];             // [B,H,S,64]
__device__ float g_k [Mtok*Dq];
__device__ float g_v [Mtok*Dq];
__device__ float g_ctx[Mtok*Dq];

// ---------------- helpers ----------------
__device__ __forceinline__ float rna_tf32(float x) {
    uint32_t r; asm("cvt.rna.tf32.f32 %0, %1;" : "=r"(r) : "f"(x));
    return __uint_as_float(r);
}
__device__ __forceinline__ float warp_max(float v) {
    #pragma unroll
    for (int o = 16; o; o >>= 1) v = fmaxf(v, __shfl_xor_sync(0xffffffffu, v, o));
    return v;
}
__device__ __forceinline__ float warp_sum(float v) {
    #pragma unroll
    for (int o = 16; o; o >>= 1) v += __shfl_xor_sync(0xffffffffu, v, o);
    return v;
}
__device__ __forceinline__ uint32_t smem_u32(const void* p) {
    uint32_t a;
    asm("{ .reg .u64 t; cvta.to.shared.u64 t, %1; cvt.u32.u64 %0, t; }" : "=r"(a) : "l"(p));
    return a;
}

#define CP16(dst, src) \
    asm volatile("cp.async.cg.shared.global [%0], [%1], 16;" :: "r"(dst), "l"(src))
#define CPCOMMIT() asm volatile("cp.async.commit_group;")
#define CPWAIT(n)  asm volatile("cp.async.wait_group %0;" :: "n"(n))

#define LDSM4(r0, r1, r2, r3, addr) \
    asm volatile("ldmatrix.sync.aligned.m8n8.x4.shared.b16 {%0,%1,%2,%3}, [%4];" \
        : "=r"(r0), "=r"(r1), "=r"(r2), "=r"(r3) : "r"(addr))

__device__ __forceinline__ void mma_tf32(float c[4], const uint32_t a[4], const uint32_t b[2]) {
    asm volatile(
        "mma.sync.aligned.m16n8k8.row.col.f32.tf32.tf32.f32 "
        "{%0,%1,%2,%3}, {%4,%5,%6,%7}, {%8,%9}, {%0,%1,%2,%3};"
        : "+f"(c[0]), "+f"(c[1]), "+f"(c[2]), "+f"(c[3])
        : "r"(a[0]), "r"(a[1]), "r"(a[2]), "r"(a[3]), "r"(b[0]), "r"(b[1]));
}

// ---------------- prep kernels ----------------
__global__ void round_copy_kernel(const float4* __restrict__ in, float4* __restrict__ out, int n4) {
    int i = blockIdx.x * blockDim.x + threadIdx.x;
    if (i < n4) {
        float4 v = in[i];
        v.x = rna_tf32(v.x); v.y = rna_tf32(v.y); v.z = rna_tf32(v.z); v.w = rna_tf32(v.w);
        out[i] = v;
    }
}

// All 7 weight transposes in ONE launch. All sources have Kdim=Dq rows.
// flattened tiles: [0,256) Wq_sel | [256,1280) Wq | [1280,2304) Wk | [2304,3328) Wv
//                  [3328,4352) Wu | [4352,5376) Wo | [5376,5632) Wk_sel
__global__ void transpose_all_kernel(
    const float* __restrict__ Wq_sel, const float* __restrict__ Wq,
    const float* __restrict__ Wk, const float* __restrict__ Wv,
    const float* __restrict__ Wu, const float* __restrict__ Wo,
    const float* __restrict__ Wk_sel,
    float* __restrict__ Wcat, float* __restrict__ WuT,
    float* __restrict__ WoT, float* __restrict__ WkselT)
{
    __shared__ float t[32][33];
    int tix = blockIdx.x;
    const float* W; float* Wt; int Ndim;
    if (tix < 256)       { W = Wq_sel; Wt = Wcat;                              Ndim = DAq; }
    else if (tix < 1280) { tix -= 256;  W = Wq; Wt = Wcat + (size_t)DAq * Dq;            Ndim = Dq; }
    else if (tix < 2304) { tix -= 1280; W = Wk; Wt = Wcat + (size_t)(DAq + Dq) * Dq;     Ndim = Dq; }
    else if (tix < 3328) { tix -= 2304; W = Wv; Wt = Wcat + (size_t)(DAq + 2 * Dq) * Dq; Ndim = Dq; }
    else if (tix < 4352) { tix -= 3328; W = Wu; Wt = WuT;                                Ndim = Dq; }
    else if (tix < 5376) { tix -= 4352; W = Wo; Wt = WoT;                                Ndim = Dq; }
    else                 { tix -= 5376; W = Wk_sel; Wt = WkselT;                         Ndim = DAq; }
    int ntile = Ndim >> 5;
    int n0 = (tix % ntile) * 32, k0 = (tix / ntile) * 32;
    int tx = threadIdx.x, ty = threadIdx.y;
    #pragma unroll
    for (int i = 0; i < 32; i += 8)
        t[ty + i][tx] = W[(size_t)(k0 + ty + i) * Ndim + n0 + tx];
    __syncthreads();
    #pragma unroll
    for (int i = 0; i < 32; i += 8)
        Wt[(size_t)(n0 + ty + i) * Dq + k0 + tx] = rna_tf32(t[tx][ty + i]);
}

__global__ void pool_kernel(const float* __restrict__ x, float* __restrict__ pooled) {
    int br = blockIdx.x;
    const float* base = x + (size_t)br * 32 * Dq;
    int d4 = threadIdx.x;
    float4 acc = make_float4(0.f, 0.f, 0.f, 0.f);
    #pragma unroll 4
    for (int i = 0; i < 32; i++) {
        float4 v = *(const float4*)(base + (size_t)i * Dq + d4 * 4);
        acc.x += v.x; acc.y += v.y; acc.z += v.z; acc.w += v.w;
    }
    const float s = 1.0f / 32.0f;
    acc.x = rna_tf32(acc.x * s); acc.y = rna_tf32(acc.y * s);
    acc.z = rna_tf32(acc.z * s); acc.w = rna_tf32(acc.w * s);
    *(float4*)(pooled + (size_t)br * Dq + d4 * 4) = acc;
}

// ---------------- big tf32 mma.sync GEMM (R6 config: 256 thr, 64x32 warp tiles) ----------------
// C[M,N] = A[M,K] @ Bt[N,K]^T
// modes: 0 plain, 2 +resid, 3 store rounded, 4 fused routing (qsel/q/k/v)
#define GBM 128
#define GBN 128
#define GBK 32
#define LDT 36
#define STG_FLOATS (GBM * LDT)       // 4608
#define SM_GEMM_BYTES (4 * STG_FLOATS * 4)

__global__ __launch_bounds__(256, 2)
void mma_gemm(const float* __restrict__ A, const float* __restrict__ Bt,
              float* __restrict__ C, int M, int N, int Kd,
              int mode, const float* __restrict__ resid,
              float* __restrict__ pq, float* __restrict__ pk, float* __restrict__ pv)
{
    extern __shared__ float smf[];
    int tid = threadIdx.x;
    int wid = tid >> 5, lane = tid & 31;
    int warp_row = wid & 1;        // 2 warps along M (64 rows each)
    int warp_col = wid >> 1;       // 4 warps along N (32 cols each)
    int gr = lane >> 2, gc = lane & 3;
    int bm = blockIdx.y * GBM;
    int bn = blockIdx.x * GBN;

    int sel = lane >> 3, l8 = lane & 7;
    int a_row_off = (sel & 1) * 8 + l8;
    int a_col_off = (sel >> 1) * 4;
    int b_row_off = (sel >> 1) * 8 + l8;
    int b_col_off = (sel & 1) * 4;

    float c[4][4][4];
    #pragma unroll
    for (int f = 0; f < 4; f++)
        #pragma unroll
        for (int g = 0; g < 4; g++)
            #pragma unroll
            for (int i = 0; i < 4; i++) c[f][g][i] = 0.f;

    uint32_t sbase = smem_u32(smf);
    const int NK = Kd / GBK;

    auto load_stage = [&](int p, int k0) {
        uint32_t Abase = sbase + (uint32_t)(p * 2 * STG_FLOATS) * 4;
        uint32_t Bbase = Abase + STG_FLOATS * 4;
        #pragma unroll
        for (int j = 0; j < 4; j++) {
            int idx = tid + j * 256;
            int row = idx >> 3, kc = idx & 7;
            CP16(Abase + (uint32_t)(row * LDT + kc * 4) * 4,
                 A + (size_t)(bm + row) * Kd + k0 + kc * 4);
        }
        #pragma unroll
        for (int j = 0; j < 4; j++) {
            int idx = tid + j * 256;
            int row = idx >> 3, kc = idx & 7;
            CP16(Bbase + (uint32_t)(row * LDT + kc * 4) * 4,
                 Bt + (size_t)(bn + row) * Kd + k0 + kc * 4);
        }
    };

    load_stage(0, 0);
    CPCOMMIT();

    for (int ks = 0; ks < NK; ks++) {
        int p = ks & 1;
        if (ks + 1 < NK) {
            load_stage(p ^ 1, (ks + 1) * GBK);
            CPCOMMIT();
            CPWAIT(1);
        } else {
            CPWAIT(0);
        }
        __syncthreads();

        uint32_t As = sbase + (uint32_t)(p * 2 * STG_FLOATS) * 4;
        uint32_t Bs = As + STG_FLOATS * 4;
        uint32_t aAddr = As + (uint32_t)((warp_row * 64 + a_row_off) * LDT + a_col_off) * 4;
        uint32_t bAddr = Bs + (uint32_t)((warp_col * 32 + b_row_off) * LDT + b_col_off) * 4;

        #pragma unroll
        for (int kk = 0; kk < 4; kk++) {
            uint32_t a[4][4], b[4][2];
            #pragma unroll
            for (int f = 0; f < 4; f++)
                LDSM4(a[f][0], a[f][1], a[f][2], a[f][3],
                      aAddr + (uint32_t)(f * 16 * LDT + kk * 8) * 4);
            #pragma unroll
            for (int gp = 0; gp < 2; gp++)
                LDSM4(b[2*gp][0], b[2*gp][1], b[2*gp+1][0], b[2*gp+1][1],
                      bAddr + (uint32_t)(gp * 16 * LDT + kk * 8) * 4);
            #pragma unroll
            for (int f = 0; f < 4; f++)
                #pragma unroll
                for (int g = 0; g < 4; g++)
                    mma_tf32(c[f][g], a[f], b[g]);
        }
        __syncthreads();
    }

    // epilogue: stage in smem, coalesced routed stores
    float* stg = smf;
    #pragma unroll
    for (int f = 0; f < 4; f++) {
        #pragma unroll
        for (int g = 0; g < 4; g++) {
            int r0 = warp_row * 64 + f * 16 + gr;
            int c0 = warp_col * 32 + g * 8 + 2 * gc;
            stg[r0 * 132 + c0]           = c[f][g][0];
            stg[r0 * 132 + c0 + 1]       = c[f][g][1];
            stg[(r0 + 8) * 132 + c0]     = c[f][g][2];
            stg[(r0 + 8) * 132 + c0 + 1] = c[f][g][3];
        }
    }
    __syncthreads();

    int ccol = (tid & 31) * 4;
    #pragma unroll 4
    for (int rr = 0; rr < 16; rr++) {
        int r = (tid >> 5) + rr * 8;
        float4 v;
        v.x = stg[r * 132 + ccol + 0];
        v.y = stg[r * 132 + ccol + 1];
        v.z = stg[r * 132 + ccol + 2];
        v.w = stg[r * 132 + ccol + 3];
        int m = bm + r;
        int n = bn + ccol;
        if (mode == 0) {
            *(float4*)(C + (size_t)m * N + n) = v;
        } else if (mode == 2) {
            float4 rv = *(const float4*)(resid + (size_t)m * N + n);
            v.x += rv.x; v.y += rv.y; v.z += rv.z; v.w += rv.w;
            *(float4*)(C + (size_t)m * N + n) = v;
        } else if (mode == 3) {
            v.x = rna_tf32(v.x); v.y = rna_tf32(v.y);
            v.z = rna_tf32(v.z); v.w = rna_tf32(v.w);
            *(float4*)(C + (size_t)m * N + n) = v;
        } else {
            if (n < DAq) {
                *(float4*)(C + (size_t)m * DAq + n) = v;
            } else {
                int n2 = n - DAq;
                int proj = n2 >> 10, nn = n2 & 1023;
                int h = nn >> 6, hd = nn & 63;
                int b = m >> 10, s = m & 1023;
                float* P = (proj == 0) ? pq : (proj == 1) ? pk : pv;
                *(float4*)(P + (((size_t)(b * Hq + h)) * Sq + s) * HDq + hd) = v;
            }
        }
    }
}

// ---------------- split-K small GEMM: 64x64 tile, 128 thr, K/4 per z-slice ----------------
#define SKLDT 36
#define SK_STAGE (128 * SKLDT)   // 64 A rows + 64 B rows

__global__ __launch_bounds__(128)
void mma_gemm_sk(const float* __restrict__ A, const float* __restrict__ Bt,
                 float* __restrict__ Cpart, int M, int N, int Kd)
{
    __shared__ float smf[2 * SK_STAGE];   // 36 KB static
    int tid = threadIdx.x;
    int wid = tid >> 5, lane = tid & 31;
    int warp_row = wid & 1;        // 2 warps along M (32 rows each)
    int warp_col = wid >> 1;       // 2 warps along N (32 cols each)
    int gr = lane >> 2, gc = lane & 3;
    int bm = blockIdx.y * 64;
    int bn = blockIdx.x * 64;
    int kslice = Kd >> 2;
    int kbase = blockIdx.z * kslice;

    int sel = lane >> 3, l8 = lane & 7;
    int a_row_off = (sel & 1) * 8 + l8;
    int a_col_off = (sel >> 1) * 4;
    int b_row_off = (sel >> 1) * 8 + l8;
    int b_col_off = (sel & 1) * 4;

    float c[2][4][4];
    #pragma unroll
    for (int f = 0; f < 2; f++)
        #pragma unroll
        for (int g = 0; g < 4; g++)
            #pragma unroll
            for (int i = 0; i < 4; i++) c[f][g][i] = 0.f;

    uint32_t sbase = smem_u32(smf);
    const int NK = kslice / GBK;   // 8

    auto load_stage = [&](int p, int k0) {
        uint32_t Abase = sbase + (uint32_t)(p * SK_STAGE) * 4;
        uint32_t Bbase = Abase + (uint32_t)(64 * SKLDT) * 4;
        #pragma unroll
        for (int j = 0; j < 4; j++) {
            int idx = tid + j * 128;   // 0..511
            int row = idx >> 3, kc = idx & 7;
            CP16(Abase + (uint32_t)(row * SKLDT + kc * 4) * 4,
                 A + (size_t)(bm + row) * Kd + k0 + kc * 4);
        }
        #pragma unroll
        for (int j = 0; j < 4; j++) {
            int idx = tid + j * 128;
            int row = idx >> 3, kc = idx & 7;
            CP16(Bbase + (uint32_t)(row * SKLDT + kc * 4) * 4,
                 Bt + (size_t)(bn + row) * Kd + k0 + kc * 4);
        }
    };

    load_stage(0, kbase);
    CPCOMMIT();

    for (int ks = 0; ks < NK; ks++) {
        int p = ks & 1;
        if (ks + 1 < NK) {
            load_stage(p ^ 1, kbase + (ks + 1) * GBK);
            CPCOMMIT();
            CPWAIT(1);
        } else {
            CPWAIT(0);
        }
        __syncthreads();

        uint32_t As = sbase + (uint32_t)(p * SK_STAGE) * 4;
        uint32_t Bs = As + (uint32_t)(64 * SKLDT) * 4;
        uint32_t aAddr = As + (uint32_t)((warp_row * 32 + a_row_off) * SKLDT + a_col_off) * 4;
        uint32_t bAddr = Bs + (uint32_t)((warp_col * 32 + b_row_off) * SKLDT + b_col_off) * 4;

        #pragma unroll
        for (int kk = 0; kk < 4; kk++) {
            uint32_t a[2][4], b[4][2];
            #pragma unroll
            for (int f = 0; f < 2; f++)
                LDSM4(a[f][0], a[f][1], a[f][2], a[f][3],
                      aAddr + (uint32_t)(f * 16 * SKLDT + kk * 8) * 4);
            #pragma unroll
            for (int gp = 0; gp < 2; gp++)
                LDSM4(b[2*gp][0], b[2*gp][1], b[2*gp+1][0], b[2*gp+1][1],
                      bAddr + (uint32_t)(gp * 16 * SKLDT + kk * 8) * 4);
            #pragma unroll
            for (int f = 0; f < 2; f++)
                #pragma unroll
                for (int g = 0; g < 4; g++)
                    mma_tf32(c[f][g], a[f], b[g]);
        }
        __syncthreads();
    }

    float* Cp = Cpart + (size_t)blockIdx.z * M * N;
    #pragma unroll
    for (int f = 0; f < 2; f++)
        #pragma unroll
        for (int g = 0; g < 4; g++) {
            int r0 = bm + warp_row * 32 + f * 16 + gr;
            int c0 = bn + warp_col * 32 + g * 8 + 2 * gc;
            *(float2*)(Cp + (size_t)r0 * N + c0)       = make_float2(c[f][g][0], c[f][g][1]);
            *(float2*)(Cp + (size_t)(r0 + 8) * N + c0) = make_float2(c[f][g][2], c[f][g][3]);
        }
}

// reduce 4 split-K partials; optional tf32 rounding
__global__ void reduce4_kernel(const float4* __restrict__ part, float4* __restrict__ dst,
                               int n4, int do_round) {
    int i = blockIdx.x * blockDim.x + threadIdx.x;
    if (i >= n4) return;
    float4 a = part[i], b = part[i + n4], cc = part[i + 2 * n4], d = part[i + 3 * n4];
    float4 v = make_float4(a.x + b.x + cc.x + d.x, a.y + b.y + cc.y + d.y,
                           a.z + b.z + cc.z + d.z, a.w + b.w + cc.w + d.w);
    if (do_round) {
        v.x = rna_tf32(v.x); v.y = rna_tf32(v.y); v.z = rna_tf32(v.z); v.w = rna_tf32(v.w);
    }
    dst[i] = v;
}

// ---------------- block selection ----------------
__global__ __launch_bounds__(256) void select_kernel(
    const float* __restrict__ qsel, const float* __restrict__ ksel,
    unsigned char* __restrict__ mask)
{
    __shared__ float ks[Rq][DAq + 1];
    __shared__ float qrow[8][DAq];
    int b = blockIdx.x;
    int s0 = blockIdx.y * 8;
    int warp = threadIdx.x >> 5, lane = threadIdx.x & 31;
    int s = s0 + warp;

    const float* kp = ksel + (size_t)b * Rq * DAq;
    for (int i = threadIdx.x; i < Rq * DAq; i += 256)
        ks[i >> 8][i & 255] = kp[i];
    const float* qp = qsel + ((size_t)b * Sq + s) * DAq;
    for (int d = lane; d < DAq; d += 32) qrow[warp][d] = qp[d];
    __syncthreads();

    float logit = 0.f;
    #pragma unroll 8
    for (int d = 0; d < DAq; d++)
        logit += qrow[warp][d] * ks[lane][d];
    logit *= 0.0625f;

    float mx = warp_max(logit);
    float e = expf(logit - mx);
    float sum = warp_sum(e);
    float prob = e / sum;
    bool own = (s >> 5) == lane;
    mask[((size_t)b * Sq + s) * Rq + lane] = (prob >= 0.5f || own) ? 1 : 0;
}

// ---------------- block-sparse attention (32 queries per CTA) ----------------
__global__ __launch_bounds__(256) void attn_kernel(
    const float* __restrict__ Q, const float* __restrict__ K,
    const float* __restrict__ V, const unsigned char* __restrict__ mask,
    float* __restrict__ ctx)
{
    __shared__ float qs[32][68];
    __shared__ float kt[32][68];
    __shared__ float vt[32][68];
    __shared__ uint32_t qbits[32];
    __shared__ uint32_t needm_s;

    int bh = blockIdx.x;
    int b = bh >> 4, h = bh & 15;
    int qb = blockIdx.y;
    int s0 = qb * 32;
    int tid = threadIdx.x, warp = tid >> 5, lane = tid & 31;

    const float* Qb = Q + ((size_t)bh * Sq + s0) * HDq;
    #pragma unroll
    for (int i = 0; i < 2; i++) {
        int idx = tid + i * 256;
        int row = idx >> 4, col = (idx & 15) << 2;
        float4 f = *(const float4*)(Qb + row * HDq + col);
        qs[row][col] = f.x; qs[row][col+1] = f.y; qs[row][col+2] = f.z; qs[row][col+3] = f.w;
    }

    if (warp == 0) {
        const unsigned char* mrow = mask + ((size_t)b * Sq + s0 + lane) * Rq;
        uint32_t bits = 0;
        #pragma unroll
        for (int r = 0; r < Rq; r++) bits |= (mrow[r] ? 1u : 0u) << r;
        qbits[lane] = bits;
        #pragma unroll
        for (int o = 16; o; o >>= 1) bits |= __shfl_xor_sync(0xffffffffu, bits, o);
        if (lane == 0) needm_s = bits;
    }
    __syncthreads();
    uint32_t need = needm_s;
    uint32_t myb[4];
    #pragma unroll
    for (int j = 0; j < 4; j++) myb[j] = qbits[warp * 4 + j];

    float mr[4], l[4], c0[4], c1[4];
    #pragma unroll
    for (int j = 0; j < 4; j++) { mr[j] = -INFINITY; l[j] = 0.f; c0[j] = 0.f; c1[j] = 0.f; }

    const float* kbh = K + (size_t)bh * Sq * HDq;
    const float* vbh = V + (size_t)bh * Sq * HDq;

    for (int r = 0; r < 32; r++) {
        if (!((need >> r) & 1u)) continue;
        __syncthreads();
        const float* kb = kbh + (size_t)r * 32 * HDq;
        const float* vb = vbh + (size_t)r * 32 * HDq;
        #pragma unroll
        for (int i = 0; i < 2; i++) {
            int idx = tid + i * 256;
            int row = idx >> 4, col = (idx & 15) << 2;
            float4 f = *(const float4*)(kb + row * HDq + col);
            kt[row][col] = f.x; kt[row][col+1] = f.y; kt[row][col+2] = f.z; kt[row][col+3] = f.w;
            float4 g = *(const float4*)(vb + row * HDq + col);
            vt[row][col] = g.x; vt[row][col+1] = g.y; vt[row][col+2] = g.z; vt[row][col+3] = g.w;
        }
        __syncthreads();

        #pragma unroll
        for (int j = 0; j < 4; j++) {
            if (!((myb[j] >> r) & 1u)) continue;
            int qi = warp * 4 + j;
            float sc = 0.f;
            #pragma unroll
            for (int d = 0; d < HDq; d += 4) {
                float4 kv = *(const float4*)&kt[lane][d];
                float4 qv = *(const float4*)&qs[qi][d];
                sc += kv.x * qv.x + kv.y * qv.y + kv.z * qv.z + kv.w * qv.w;
            }
            sc *= 0.125f;
            float bmax = warp_max(sc);
            float mnew = fmaxf(mr[j], bmax);
            float p = __expf(sc - mnew);
            float scale = __expf(mr[j] - mnew);
            l[j] = l[j] * scale + warp_sum(p);
            c0[j] *= scale; c1[j] *= scale;
            #pragma unroll 8
            for (int t = 0; t < 32; t++) {
                float pj = __shfl_sync(0xffffffffu, p, t);
                c0[j] += pj * vt[t][lane];
                c1[j] += pj * vt[t][lane + 32];
            }
            mr[j] = mnew;
        }
    }

    #pragma unroll
    for (int j = 0; j < 4; j++) {
        int s = s0 + warp * 4 + j;
        float inv = 1.0f / l[j];
        float* cp = ctx + ((size_t)(b * Sq + s)) * Dq + h * HDq;
        cp[lane] = rna_tf32(c0[j] * inv);
        cp[lane + 32] = rna_tf32(c1[j] * inv);
    }
}

// ---------------- host launch ----------------
extern "C" void kernel_launch(void* const* d_in, const int* in_sizes, int n_in,
                              void* d_out, int out_size) {
    const float* x      = (const float*)d_in[0];
    const float* Wu     = (const float*)d_in[1];
    const float* Wk_sel = (const float*)d_in[2];
    const float* Wq_sel = (const float*)d_in[3];
    const float* Wq     = (const float*)d_in[4];
    const float* Wk     = (const float*)d_in[5];
    const float* Wv     = (const float*)d_in[6];
    const float* Wo     = (const float*)d_in[7];
    float* out = (float*)d_out;

    float *xr, *WuT, *WoT, *WkselT, *Wcat, *part;
    float *pooled, *root, *ksel, *qsel, *q, *k, *v, *ctx;
    unsigned char* mask;
    cudaGetSymbolAddress((void**)&xr,     g_xr);
    cudaGetSymbolAddress((void**)&WuT,    g_WuT);
    cudaGetSymbolAddress((void**)&WoT,    g_WoT);
    cudaGetSymbolAddress((void**)&WkselT, g_WkselT);
    cudaGetSymbolAddress((void**)&Wcat,   g_Wcat);
    cudaGetSymbolAddress((void**)&part,   g_part);
    cudaGetSymbolAddress((void**)&pooled, g_pooled);
    cudaGetSymbolAddress((void**)&root,   g_root);
    cudaGetSymbolAddress((void**)&ksel,   g_ksel);
    cudaGetSymbolAddress((void**)&qsel,   g_qsel);
    cudaGetSymbolAddress((void**)&mask,   g_mask);
    cudaGetSymbolAddress((void**)&q,      g_q);
    cudaGetSymbolAddress((void**)&k,      g_k);
    cudaGetSymbolAddress((void**)&v,      g_v);
    cudaGetSymbolAddress((void**)&ctx,    g_ctx);

    cudaFuncSetAttribute(mma_gemm, cudaFuncAttributeMaxDynamicSharedMemorySize, SM_GEMM_BYTES);

    // (1) round x
    round_copy_kernel<<<(Mtok * Dq / 4 + 255) / 256, 256>>>((const float4*)x, (float4*)xr, Mtok * Dq / 4);
    // (2) all weight transposes in one launch
    transpose_all_kernel<<<5632, dim3(32, 8)>>>(Wq_sel, Wq, Wk, Wv, Wu, Wo, Wk_sel,
                                                Wcat, WuT, WoT, WkselT);
    // (3) pooling
    pool_kernel<<<Bq * Rq, 256>>>(x, pooled);
    // (4-5) root = pooled @ Wu (split-K 4 + rounded reduce)
    mma_gemm_sk<<<dim3(Dq / 64, (Bq * Rq) / 64, 4), 128>>>(pooled, WuT, part, Bq * Rq, Dq, Dq);
    reduce4_kernel<<<(Bq * Rq * Dq / 4 + 255) / 256, 256>>>((const float4*)part, (float4*)root,
                                                            Bq * Rq * Dq / 4, 1);
    // (6-7) ksel = root @ Wk_sel (split-K 4 + plain reduce)
    mma_gemm_sk<<<dim3(DAq / 64, (Bq * Rq) / 64, 4), 128>>>(root, WkselT, part, Bq * Rq, DAq, Dq);
    reduce4_kernel<<<(Bq * Rq * DAq / 4 + 255) / 256, 256>>>((const float4*)part, (float4*)ksel,
                                                             Bq * Rq * DAq / 4, 0);
    // (8) fused: [qsel | q | k | v] = xr @ Wcat^T
    mma_gemm<<<dim3(NCAT / GBN, Mtok / GBM), 256, SM_GEMM_BYTES>>>(
        xr, Wcat, qsel, Mtok, NCAT, Dq, 4, nullptr, q, k, v);
    // (9) selection mask
    select_kernel<<<dim3(Bq, Sq / 8), 256>>>(qsel, ksel, mask);
    // (10) attention
    attn_kernel<<<dim3(Bq * Hq, Sq / 32), 256>>>(q, k, v, mask, ctx);
    // (11) out = ctx @ Wo + x
    mma_gemm<<<dim3(Dq / GBN, Mtok / GBM), 256, SM_GEMM_BYTES>>>(
        ctx, WoT, out, Mtok, Dq, Dq, 2, x, nullptr, nullptr, nullptr);
}